// round 6
// baseline (speedup 1.0000x reference)
#include <cuda_runtime.h>
#include <cuda_fp16.h>

#define B_     2
#define N_IN_  262144
#define D_     32
#define N_OUT_ 65536
#define K_     4
#define NK_    9
#define TOTAL_ (B_ * N_OUT_ * K_)     // 524288 outputs

// sigma-dedup + interleaved coords + fp16 feature copy
__device__ float  g_uc0;                    // 1/(2*sigma^2) when uniform
__device__ int    g_u;                      // 1 = uniform sigma, 2 = general
__device__ float2 g_c2[B_ * N_IN_];         // (cx, cy) per input point
__device__ __half g_xh[B_ * N_IN_ * D_];    // fp16 features, 64B rows

// ---------------- prep: sigma check + coord pack + fp16 repack ----------------
// 1,048,576 threads; each repacks 16 floats (4 independent LDG.128 -> 2 STG.128).
__global__ void __launch_bounds__(256) prep_kernel(
    const float* __restrict__ x,
    const float* __restrict__ sigma,
    const float* __restrict__ cin)
{
    const int tid = blockIdx.x * blockDim.x + threadIdx.x;

    if (blockIdx.x == 0 && threadIdx.x < 32) {
        float s = sigma[threadIdx.x];
        float c = 1.0f / (2.0f * s * s);
        float c0 = __shfl_sync(0xffffffffu, c, 0);
        unsigned same = __ballot_sync(0xffffffffu, c == c0);
        if (threadIdx.x == 0) {
            g_u   = (same == 0xffffffffu) ? 1 : 2;
            g_uc0 = c0;
        }
    }

    {
        const float4* x4 = (const float4*)x;
        float4 a0 = __ldg(&x4[tid * 4 + 0]);
        float4 a1 = __ldg(&x4[tid * 4 + 1]);
        float4 a2 = __ldg(&x4[tid * 4 + 2]);
        float4 a3 = __ldg(&x4[tid * 4 + 3]);
        __half2 h0 = __floats2half2_rn(a0.x, a0.y);
        __half2 h1 = __floats2half2_rn(a0.z, a0.w);
        __half2 h2 = __floats2half2_rn(a1.x, a1.y);
        __half2 h3 = __floats2half2_rn(a1.z, a1.w);
        __half2 h4 = __floats2half2_rn(a2.x, a2.y);
        __half2 h5 = __floats2half2_rn(a2.z, a2.w);
        __half2 h6 = __floats2half2_rn(a3.x, a3.y);
        __half2 h7 = __floats2half2_rn(a3.z, a3.w);
        uint4 p0, p1;
        p0.x = *(const unsigned*)&h0;  p0.y = *(const unsigned*)&h1;
        p0.z = *(const unsigned*)&h2;  p0.w = *(const unsigned*)&h3;
        p1.x = *(const unsigned*)&h4;  p1.y = *(const unsigned*)&h5;
        p1.z = *(const unsigned*)&h6;  p1.w = *(const unsigned*)&h7;
        ((uint4*)g_xh)[tid * 2 + 0] = p0;
        ((uint4*)g_xh)[tid * 2 + 1] = p1;
    }

    if (tid < (B_ * N_IN_) / 4) {
        float4 cx = __ldg(&((const float4*)cin)[tid]);
        float4 cy = __ldg(&((const float4*)(cin + B_ * N_IN_))[tid]);
        float4* dst = (float4*)g_c2;
        dst[tid * 2 + 0] = make_float4(cx.x, cy.x, cx.y, cy.y);
        dst[tid * 2 + 1] = make_float4(cx.z, cy.z, cx.w, cy.w);
    }
}

// ---------------- uniform-sigma hot kernel: 8 outputs per warp ----------------
// lane = 4g + m: g = output within warp (0..7), m = channel quad (uint4 = 8 fp16).
// Lane 4g+m owns coord pairs (g, j) for j = m, m+4, and (m==0) j=8.
__global__ void __launch_bounds__(256) proj_uniform_kernel(
    const float* __restrict__ cout,   // (2, B, N_OUT, K)
    const int*   __restrict__ nidx,   // (B, N_OUT, K, NK)
    float* __restrict__ out)          // (B, N_OUT*K, D)
{
    if (g_u != 1) return;

    const unsigned lane = threadIdx.x & 31u;
    const int w    = (int)((blockIdx.x * (unsigned)blockDim.x + threadIdx.x) >> 5);
    const int bnk0 = w * 8;
    const int g    = (int)(lane >> 2);
    const int m    = (int)(lane & 3u);
    const int bnk  = bnk0 + g;
    const int b    = bnk0 >> 18;

    // idx loads: 3 slots owned by this lane (slot2 only on m==0)
    const size_t nb = (size_t)bnk * NK_;
    int i0 = __ldg(&nidx[nb + m]);
    int i1 = __ldg(&nidx[nb + m + 4]);
    int i2 = (m == 0) ? __ldg(&nidx[nb + 8]) : 0;

    // broadcast all 9 neighbor indices of output g (1 SHFL each, slot is compile-time)
    const unsigned gbase = lane & 28u;
    int ij[NK_];
#pragma unroll
    for (int j = 0; j < NK_; j++) {
        int v = (j < 4) ? i0 : (j < 8) ? i1 : i2;
        ij[j] = __shfl_sync(0xffffffffu, v, (int)(gbase | (j & 3)));
    }

    // issue 9 feature gathers early (LDG.128: 8 rows x 16B per warp)
    const uint4* xb = (const uint4*)g_xh + (size_t)b * N_IN_ * (D_ / 8) + m;
    uint4 f[NK_];
#pragma unroll
    for (int j = 0; j < NK_; j++) f[j] = __ldg(xb + (size_t)ij[j] * (D_ / 8));

    // coords + squared distances for owned pairs
    float ox = __ldg(&cout[bnk]);
    float oy = __ldg(&cout[bnk + TOTAL_]);
    float2 c0 = g_c2[b * N_IN_ + i0];
    float2 c1 = g_c2[b * N_IN_ + i1];
    float dx0 = ox - c0.x, dy0 = oy - c0.y;
    float dx1 = ox - c1.x, dy1 = oy - c1.y;
    float t0 = -(dx0 * dx0 + dy0 * dy0);
    float t1 = -(dx1 * dx1 + dy1 * dy1);
    float t2 = 0.0f;
    if (m == 0) {
        float2 c2v = g_c2[b * N_IN_ + i2];
        float dx2 = ox - c2v.x, dy2 = oy - c2v.y;
        t2 = -(dx2 * dx2 + dy2 * dy2);
    }
    const float cu = g_uc0;
    float e0 = __expf(t0 * cu);
    float e1 = __expf(t1 * cu);
    float e2 = __expf(t2 * cu);   // only lanes m==0 hold valid e2

    // weights + accumulate 8 channels
    float a0 = 0.f, a1 = 0.f, a2 = 0.f, a3 = 0.f;
    float a4 = 0.f, a5 = 0.f, a6 = 0.f, a7 = 0.f;
    float den = 1e-9f;
#pragma unroll
    for (int j = 0; j < NK_; j++) {
        float ev = (j < 4) ? e0 : (j < 8) ? e1 : e2;
        float wj = __shfl_sync(0xffffffffu, ev, (int)(gbase | (j & 3)));
        float2 p0 = __half22float2(*(const __half2*)&f[j].x);
        float2 p1 = __half22float2(*(const __half2*)&f[j].y);
        float2 p2 = __half22float2(*(const __half2*)&f[j].z);
        float2 p3 = __half22float2(*(const __half2*)&f[j].w);
        a0 = fmaf(wj, p0.x, a0);  a1 = fmaf(wj, p0.y, a1);
        a2 = fmaf(wj, p1.x, a2);  a3 = fmaf(wj, p1.y, a3);
        a4 = fmaf(wj, p2.x, a4);  a5 = fmaf(wj, p2.y, a5);
        a6 = fmaf(wj, p3.x, a6);  a7 = fmaf(wj, p3.y, a7);
        den += wj;
    }
    float inv = __fdividef(1.0f, den);
    float* dst = out + (size_t)bnk * D_ + m * 8;
    ((float4*)dst)[0] = make_float4(a0 * inv, a1 * inv, a2 * inv, a3 * inv);
    ((float4*)dst)[1] = make_float4(a4 * inv, a5 * inv, a6 * inv, a7 * inv);
}

// ---------------- general-sigma fallback: 4 outputs per warp (R4 layout) ------
__global__ void __launch_bounds__(256) proj_general_kernel(
    const float* __restrict__ cout,
    const float* __restrict__ sigma,
    const int*   __restrict__ nidx,
    float* __restrict__ out)
{
    if (g_u == 1) return;

    const unsigned lane = threadIdx.x & 31u;
    const int w    = (int)((blockIdx.x * (unsigned)blockDim.x + threadIdx.x) >> 5);
    const int bnk0 = w * 4;
    const int g    = (int)(lane >> 3);
    const int sl   = (int)(lane & 7u);
    const int bnk  = bnk0 + g;
    const int b    = bnk0 >> 18;

    int   idxA = 0, idxB = 0;
    float tA = 0.0f, tB = 0.0f;
    if (lane < 2 * NK_) {
        const int o = (lane >= NK_) ? 1 : 0;
        const int j = (int)lane - o * NK_;
        const int oA = bnk0 + o;
        idxA = __ldg(&nidx[(size_t)oA * NK_ + j]);
        const int oB = bnk0 + 2 + o;
        idxB = __ldg(&nidx[(size_t)oB * NK_ + j]);
        float2 cA = g_c2[b * N_IN_ + idxA];
        float2 cB = g_c2[b * N_IN_ + idxB];
        float oxA = __ldg(&cout[oA]);
        float oyA = __ldg(&cout[oA + TOTAL_]);
        float oxB = __ldg(&cout[oB]);
        float oyB = __ldg(&cout[oB + TOTAL_]);
        float dxA = oxA - cA.x, dyA = oyA - cA.y;
        float dxB = oxB - cB.x, dyB = oyB - cB.y;
        tA = -(dxA * dxA + dyA * dyA);
        tB = -(dxB * dxB + dyB * dyB);
    }

    const int selbase = (g & 1) * NK_;
    int ij[NK_];
#pragma unroll
    for (int j = 0; j < NK_; j++) {
        int a  = __shfl_sync(0xffffffffu, idxA, selbase + j);
        int bb = __shfl_sync(0xffffffffu, idxB, selbase + j);
        ij[j] = (g < 2) ? a : bb;
    }

    const uint2* xb = (const uint2*)g_xh + (size_t)b * N_IN_ * (D_ / 4) + sl;
    uint2 f[NK_];
#pragma unroll
    for (int j = 0; j < NK_; j++) f[j] = __ldg(xb + (size_t)ij[j] * (D_ / 4));

    float4 s4 = ((const float4*)sigma)[sl];
    float c0 = 1.0f / (2.0f * s4.x * s4.x);
    float c1 = 1.0f / (2.0f * s4.y * s4.y);
    float c2 = 1.0f / (2.0f * s4.z * s4.z);
    float c3 = 1.0f / (2.0f * s4.w * s4.w);
    float4 num = make_float4(0.f, 0.f, 0.f, 0.f);
    float d0 = 1e-9f, d1 = 1e-9f, d2 = 1e-9f, d3 = 1e-9f;
#pragma unroll
    for (int j = 0; j < NK_; j++) {
        float ta = __shfl_sync(0xffffffffu, tA, selbase + j);
        float tb = __shfl_sync(0xffffffffu, tB, selbase + j);
        float tv = (g < 2) ? ta : tb;
        float w0 = __expf(tv * c0);
        float w1 = __expf(tv * c1);
        float w2 = __expf(tv * c2);
        float w3 = __expf(tv * c3);
        float2 lo = __half22float2(*(const __half2*)&f[j].x);
        float2 hi = __half22float2(*(const __half2*)&f[j].y);
        num.x = fmaf(w0, lo.x, num.x);
        num.y = fmaf(w1, lo.y, num.y);
        num.z = fmaf(w2, hi.x, num.z);
        num.w = fmaf(w3, hi.y, num.w);
        d0 += w0; d1 += w1; d2 += w2; d3 += w3;
    }
    float4 r = make_float4(__fdividef(num.x, d0), __fdividef(num.y, d1),
                           __fdividef(num.z, d2), __fdividef(num.w, d3));
    ((float4*)(out + (size_t)bnk * D_))[sl] = r;
}

extern "C" void kernel_launch(void* const* d_in, const int* in_sizes, int n_in,
                              void* d_out, int out_size) {
    const float* x     = (const float*)d_in[0];
    const float* cin   = (const float*)d_in[1];
    const float* cout  = (const float*)d_in[2];
    const float* sigma = (const float*)d_in[3];
    const int*   nidx  = (const int*)d_in[4];
    float* out = (float*)d_out;

    prep_kernel<<<(B_ * N_IN_ * D_) / 16 / 256, 256>>>(x, sigma, cin);

    // uniform hot path: 8 outputs/warp -> 65536 warps -> 8192 blocks
    proj_uniform_kernel<<<TOTAL_ / 8 / 8, 256>>>(cout, nidx, out);
    // general fallback: 4 outputs/warp -> 131072 warps -> 16384 blocks (early-exits)
    proj_general_kernel<<<TOTAL_ / 4 / 8, 256>>>(cout, sigma, nidx, out);
}